// round 3
// baseline (speedup 1.0000x reference)
#include <cuda_runtime.h>

// Problem constants (from reference)
#define NN 64
#define CC 256
#define HH 56
#define WW 56
#define EMBED 16
#define INDEX_K 16              // ceil(256^0.5) = 16
#define HW (HH * WW)            // 3136
#define HW4 (HW / 4)            // 784 float4 per (n,c) slab
#define SCALE (256.0f / 240.0f) // c / (c - INDEX)

// Fused kernel: one block per (n,c) slab.
//  - Issue the slab's 4 float4 DRAM loads first (front-batched, MLP=4).
//  - While in flight: thread t computes activ[n][t] AND (redundantly,
//    uniform-broadcast loads) activ[n][c]. Rank via ONE __syncthreads_count.
//  - Scale registers, store. No shared memory, single barrier.
__global__ void __launch_bounds__(256) fused_kernel(const float4* __restrict__ x,
                                                    const float* __restrict__ embeds,
                                                    const float* __restrict__ table,
                                                    float4* __restrict__ out) {
    const int nc = blockIdx.x;
    const int n = nc >> 8;       // sample
    const int c = nc & 255;      // channel this block scales
    const int t = threadIdx.x;

    const long long base = (long long)nc * HW4;
    const float4* __restrict__ xin = x + base;
    float4* __restrict__ o = out + base;

    // ---- front-batched DRAM loads ----
    const bool tail = (t < (HW4 - 3 * 256));   // 784 = 3*256 + 16
    float4 v0 = xin[t];
    float4 v1 = xin[t + 256];
    float4 v2 = xin[t + 512];
    float4 v3;
    if (tail) v3 = xin[t + 768];

    // ---- mask, overlapped under the loads above ----
    // a  = activ[n][t]   (per-thread channel)
    // ac = activ[n][c]   (block's channel; same addresses in every thread -> broadcast)
    float a = 0.0f, ac = 0.0f;
#pragma unroll
    for (int e = 0; e < EMBED; ++e) {
        const float emb = __ldg(embeds + n * EMBED + e);
        a  += emb * __ldg(table + e * CC + t);
        ac += emb * __ldg(table + e * CC + c);
    }
    // keep <=> #{j : activ[j] <= activ[c]} >= INDEX_K+1  (tie-safe; == sorted[16] <= activ[c])
    const int cnt = __syncthreads_count(a <= ac);
    const float m = (cnt >= INDEX_K + 1) ? SCALE : 0.0f;

    // ---- scale + store ----
    v0.x *= m; v0.y *= m; v0.z *= m; v0.w *= m;
    v1.x *= m; v1.y *= m; v1.z *= m; v1.w *= m;
    v2.x *= m; v2.y *= m; v2.z *= m; v2.w *= m;
    o[t]       = v0;
    o[t + 256] = v1;
    o[t + 512] = v2;
    if (tail) {
        v3.x *= m; v3.y *= m; v3.z *= m; v3.w *= m;
        o[t + 768] = v3;
    }
}

extern "C" void kernel_launch(void* const* d_in, const int* in_sizes, int n_in,
                              void* d_out, int out_size) {
    const float* x      = (const float*)d_in[0];  // [64,256,56,56]
    const float* embeds = (const float*)d_in[1];  // [64,16]
    const float* table  = (const float*)d_in[2];  // [16,256]
    float* out = (float*)d_out;

    fused_kernel<<<NN * CC, 256>>>((const float4*)x, embeds, table, (float4*)out);
}